// round 4
// baseline (speedup 1.0000x reference)
#include <cuda_runtime.h>

#define BS    64
#define SL    8192
#define EDIM  64
#define DDIM  64
#define VOCAB 1088
#define NVAL  64
#define SPLIT 16
#define CHUNK (SL / SPLIT)          // 512
// 256 threads/block, 2 elements per thread via int2 loads

// Scratch (no allocations allowed in kernel_launch)
__device__ float g_SK[BS * VOCAB];
__device__ float g_SV[BS * NVAL];
__device__ float g_Pz[BS * SPLIT];
__device__ float g_Pb[BS * SPLIT * NVAL];
__device__ int   g_cnt[BS];   // zero-init; reset by combining block each launch

// ---------------------------------------------------------------------------
// Kernel A: build per-batch score tables. One reusable 16.6KB shared buffer
// cycles through Wq -> Wk_hi -> embK-tile so every inner loop is shared-only.
//   Q[b,d]  = embK[q[b]] . Wq_w[d,:] + Wq_b[d]
//   Qk[b,e] = 0.125 * sum_d Wk_w[d,64+e] * Q[b,d]
//   SV[b,n] = 0.125 * sum_d Wk_w[d,n]    * Q[b,d]   (vt==0 blocks only)
//   SK[b,v] = embK[v] . Qk[b]
// grid = 17 vocab-tiles (64 rows) x 4 batch-tiles (16 batches), 256 threads.
// ---------------------------------------------------------------------------
__global__ __launch_bounds__(256) void tables_kernel(
    const int*   __restrict__ q,
    const float* __restrict__ embK,
    const float* __restrict__ Wk_w,   // (64, 128) row-major
    const float* __restrict__ Wq_w,   // (64, 64) row-major
    const float* __restrict__ Wq_b)
{
    const int bt = blockIdx.x & 3;      // batch tile (16 batches)
    const int vt = blockIdx.x >> 2;     // vocab tile (64 rows)
    const int b0 = bt * 16;
    const int v0 = vt * 64;
    const int tid = threadIdx.x;

    __shared__ float big[64 * 65];      // reused: Wq -> Wk_hi -> embK tile (padded)
    __shared__ float Eq [16 * 64];      // embK rows of the 16 queries
    __shared__ float Qs [16 * 64];
    __shared__ float Qks[16 * 64];
    __shared__ int   qsh[16];

    // Stage A: Wq (padded) + query indices + query embedding rows
    if (tid < 16) qsh[tid] = q[b0 + tid];
    for (int i = tid; i < 64 * 64; i += 256)
        big[(i >> 6) * 65 + (i & 63)] = Wq_w[i];
    __syncthreads();
    for (int i = tid; i < 16 * 64; i += 256)
        Eq[i] = embK[(size_t)qsh[i >> 6] * EDIM + (i & 63)];
    __syncthreads();

    // Phase 1: Q = Eq . Wq rows + bias (Eq broadcast, big stride-65 conflict-free)
    for (int idx = tid; idx < 1024; idx += 256) {
        const int bl = idx >> 6, d = idx & 63;
        float acc = Wq_b[d];
        #pragma unroll
        for (int e = 0; e < EDIM; e++)
            acc = fmaf(Eq[bl * 64 + e], big[d * 65 + e], acc);
        Qs[idx] = acc;
    }
    __syncthreads();

    // Stage B: Wk_hi (columns 64..127) into big, coalesced
    for (int i = tid; i < 64 * 64; i += 256)
        big[(i >> 6) * 65 + (i & 63)] = Wk_w[(i >> 6) * 128 + 64 + (i & 63)];
    __syncthreads();

    // Phase 2: Qk (shared-only). vt==0 blocks also emit SV (global Wk_lo, 4 blocks)
    for (int idx = tid; idx < 1024; idx += 256) {
        const int bl = idx >> 6, e = idx & 63;
        float acc = 0.f;
        #pragma unroll
        for (int d = 0; d < DDIM; d++)
            acc = fmaf(big[d * 65 + e], Qs[bl * 64 + d], acc);
        Qks[idx] = acc * 0.125f;
    }
    if (vt == 0) {
        for (int idx = tid; idx < 1024; idx += 256) {
            const int bl = idx >> 6, n = idx & 63;
            float acc = 0.f;
            #pragma unroll
            for (int d = 0; d < DDIM; d++)
                acc = fmaf(Wk_w[d * 128 + n], Qs[bl * 64 + d], acc);
            g_SV[(b0 + bl) * NVAL + n] = acc * 0.125f;
        }
    }
    __syncthreads();

    // Stage C: embK vocab tile into big, coalesced
    for (int i = tid; i < 64 * 64; i += 256)
        big[(i >> 6) * 65 + (i & 63)] = embK[(size_t)v0 * EDIM + i];
    __syncthreads();

    // Phase 3: SK tile, register-tiled 4 bl per thread (halves LDS traffic).
    {
        const int vl  = tid & 63;
        const int blq = tid >> 6;       // 0..3
        float acc[4] = {0.f, 0.f, 0.f, 0.f};
        #pragma unroll
        for (int e = 0; e < EDIM; e++) {
            const float ev = big[vl * 65 + e];
            #pragma unroll
            for (int j = 0; j < 4; j++)
                acc[j] = fmaf(ev, Qks[(blq + 4 * j) * 64 + e], acc[j]);
        }
        #pragma unroll
        for (int j = 0; j < 4; j++) {
            const int bl = blq + 4 * j;
            g_SK[(size_t)(b0 + bl) * VOCAB + v0 + vl] = acc[j];
        }
    }
}

// ---------------------------------------------------------------------------
// Kernel B: streaming exp-histogram (no max subtraction; scores are O(±6)).
// grid = 64 batches x 16 splits (1024 blocks), 256 threads, 2 elems/thread.
// Index loads are issued BEFORE the table fill so DRAM latency overlaps it.
// Last block per batch linearly combines the 16 partials.
// ---------------------------------------------------------------------------
__global__ __launch_bounds__(256) void attn_kernel(
    const int* __restrict__ x,
    float*     __restrict__ out)
{
    const int b    = blockIdx.x >> 4;
    const int sp   = blockIdx.x & 15;
    const int tid  = threadIdx.x;
    const int warp = tid >> 5;
    const int lane = tid & 31;

    __shared__ float SKs[VOCAB];
    __shared__ float SVs[NVAL];
    __shared__ float bins[8][NVAL];     // warp-replicated histograms
    __shared__ float red[8];
    __shared__ int   lastFlag;

    // Prefetch index data first (DRAM) — overlaps the table fill below (L2)
    const int* kp = x + (size_t)b * 2 * SL + sp * CHUNK;
    const int* vp = kp + SL;
    const int2 k2 = reinterpret_cast<const int2*>(kp)[tid];
    const int2 w2 = reinterpret_cast<const int2*>(vp)[tid];

    // Table fill (vectorized, from L2)
    {
        const float4* src = reinterpret_cast<const float4*>(g_SK + (size_t)b * VOCAB);
        float4* dst = reinterpret_cast<float4*>(SKs);
        for (int i = tid; i < VOCAB / 4; i += 256) dst[i] = src[i];
    }
    if (tid < NVAL) SVs[tid] = g_SV[b * NVAL + tid];
    for (int i = tid; i < 8 * NVAL; i += 256) (&bins[0][0])[i] = 0.f;
    __syncthreads();

    const int v0 = w2.x - NVAL, v1 = w2.y - NVAL;
    const float e0 = __expf(SKs[k2.x] + SVs[v0]);
    const float e1 = __expf(SKs[k2.y] + SVs[v1]);
    float z = e0 + e1;
    atomicAdd(&bins[warp][v0], e0);
    atomicAdd(&bins[warp][v1], e1);

    #pragma unroll
    for (int o = 16; o > 0; o >>= 1) z += __shfl_xor_sync(0xffffffffu, z, o);
    if (lane == 0) red[warp] = z;
    __syncthreads();

    if (tid < NVAL) {
        float bsum = 0.f;
        #pragma unroll
        for (int w = 0; w < 8; w++) bsum += bins[w][tid];
        g_Pb[(b * SPLIT + sp) * NVAL + tid] = bsum;
    }
    if (tid == 0) {
        float Z = 0.f;
        #pragma unroll
        for (int w = 0; w < 8; w++) Z += red[w];
        g_Pz[b * SPLIT + sp] = Z;
    }
    __syncthreads();

    if (tid == 0) {
        __threadfence();                            // publish partials (release)
        const int old = atomicAdd(&g_cnt[b], 1);
        lastFlag = (old == SPLIT - 1) ? 1 : 0;
        __threadfence();                            // acquire for the reads below
    }
    __syncthreads();

    if (lastFlag) {
        if (tid < NVAL) {
            volatile float* vPz = g_Pz + b * SPLIT;
            volatile float* vPb = g_Pb + (size_t)b * SPLIT * NVAL;
            float Zt = 0.f, num = 0.f;
            #pragma unroll
            for (int s2 = 0; s2 < SPLIT; s2++) {
                Zt  += vPz[s2];
                num += vPb[s2 * NVAL + tid];
            }
            out[b * NVAL + tid] = num / Zt;
        }
        __syncthreads();
        if (tid == 0) g_cnt[b] = 0;                 // re-arm for next replay
    }
}

// ---------------------------------------------------------------------------
// Inputs (metadata order): x(int32), q(int32), embK, Wk_w, Wk_b, Wq_w, Wq_b.
// Wk_b is softmax-invariant (constant per batch) and intentionally unused.
// ---------------------------------------------------------------------------
extern "C" void kernel_launch(void* const* d_in, const int* in_sizes, int n_in,
                              void* d_out, int out_size)
{
    const int*   x    = (const int*)  d_in[0];
    const int*   q    = (const int*)  d_in[1];
    const float* embK = (const float*)d_in[2];
    const float* Wk_w = (const float*)d_in[3];
    const float* Wq_w = (const float*)d_in[5];
    const float* Wq_b = (const float*)d_in[6];
    float* out = (float*)d_out;

    tables_kernel<<<68, 256>>>(q, embK, Wk_w, Wq_w, Wq_b);
    attn_kernel<<<BS * SPLIT, 256>>>(x, out);
}